// round 8
// baseline (speedup 1.0000x reference)
#include <cuda_runtime.h>
#include <stdint.h>

#define IN_F   4096
#define OUT_F  11008
#define BITS   4
#define GROUP  128

#define CHUNK    128                 // inputs per block = one dequant group
#define NCHUNK   (IN_F / CHUNK)      // 32
#define OPT      2                   // outputs per thread
#define THREADS  256
#define TILE_O   (THREADS * OPT)     // 512
#define NTILE    ((OUT_F + TILE_O - 1) / TILE_O)   // 22 (last block partial)
#define NTAB     (CHUNK / 8)         // 16 tables of 256 entries
#define NWORDS   (CHUNK / 32)        // 4 packed words per block

__global__ void __launch_bounds__(THREADS, 8) lutgemm_kernel(
    const float*    __restrict__ x,
    const uint32_t* __restrict__ qweight,
    const float*    __restrict__ alpha,
    const float*    __restrict__ qbias,
    float*          __restrict__ out)
{
    __shared__ float lut[NTAB * 256];      // 16 KB of sign-sum tables
    __shared__ float xs[CHUNK];
    __shared__ float ws[CHUNK / 32];

    const int t     = threadIdx.x;
    const int chunk = blockIdx.y;                    // 128-input group index
    const int o0    = blockIdx.x * TILE_O + 2 * t;   // this thread's 2 outputs

    // ---- stage x chunk + group sum (for the q_bias term) ----
    if (t < CHUNK) {
        float v = x[chunk * CHUNK + t];
        xs[t] = v;
        #pragma unroll
        for (int s = 16; s; s >>= 1) v += __shfl_down_sync(0xffffffffu, v, s);
        if ((t & 31) == 0) ws[t >> 5] = v;
    }
    __syncthreads();
    const float Sc = ws[0] + ws[1] + ws[2] + ws[3];   // group sum of x

    // ---- build LUTs: 256 threads x 16 gray-code-consecutive entries ----
    // Table tb covers inputs [chunk*128 + tb*8, +8); T[v] = sum_j (2*bit_j(v)-1)*x_j
    {
        const int tb = t >> 4;                 // 0..15
        const int s0 = (t & 15) * 16;          // run start (multiple of 16)
        const uint32_t g0 = (uint32_t)s0 ^ ((uint32_t)s0 >> 1);

        float x2[8];
        #pragma unroll
        for (int j = 0; j < 8; ++j) x2[j] = 2.0f * xs[tb * 8 + j];

        float acc = 0.0f;
        #pragma unroll
        for (int j = 0; j < 8; ++j)
            acc += ((g0 >> j) & 1u) ? 0.5f * x2[j] : -0.5f * x2[j];

        float* T = lut + tb * 256;
        T[g0] = acc;

        #pragma unroll
        for (int j = 1; j < 16; ++j) {
            const int k = (j & 1) ? 0 : (j & 2) ? 1 : (j & 4) ? 2 : 3;  // ctz(j)
            const uint32_t g = g0 ^ (uint32_t)(j ^ (j >> 1));           // gray(s0+j)
            acc += ((g >> k) & 1u) ? x2[k] : -x2[k];
            T[g] = acc;
        }
    }
    __syncthreads();

    if (o0 >= OUT_F) return;   // only last o-tile has idle threads

    // ---- main lookup loop: 4 words x 4 bitplanes x 2 outputs x 4 bytes ----
    float2 p0 = {0.f, 0.f}, p1 = {0.f, 0.f}, p2 = {0.f, 0.f}, p3 = {0.f, 0.f};

    #pragma unroll
    for (int wl = 0; wl < NWORDS; ++wl) {
        const int w = chunk * NWORDS + wl;
        const char* Tb = (const char*)(lut + wl * (4 * 256));
        const long base = (long)(w * BITS) * OUT_F + o0;

        const uint2 q0 = __ldg((const uint2*)(qweight + base));
        const uint2 q1 = __ldg((const uint2*)(qweight + base + OUT_F));
        const uint2 q2 = __ldg((const uint2*)(qweight + base + 2 * OUT_F));
        const uint2 q3 = __ldg((const uint2*)(qweight + base + 3 * OUT_F));

        #define LKP(dst, v)                                                     \
            dst += *(const float*)(Tb        + (((v) <<  2) & 0x3FCu))          \
                 + *(const float*)(Tb + 1024 + (((v) >>  6) & 0x3FCu))          \
                 + *(const float*)(Tb + 2048 + (((v) >> 14) & 0x3FCu))          \
                 + *(const float*)(Tb + 3072 + (((v) >> 22) & 0x3FCu))

        LKP(p0.x, q0.x); LKP(p0.y, q0.y);
        LKP(p1.x, q1.x); LKP(p1.y, q1.y);
        LKP(p2.x, q2.x); LKP(p2.y, q2.y);
        LKP(p3.x, q3.x); LKP(p3.y, q3.y);
        #undef LKP
    }

    // ---- epilogue: alpha, q_bias (one group per block), atomic accumulate ----
    const long ab = (long)(chunk * BITS) * OUT_F + o0;
    const float2 a0 = __ldg((const float2*)(alpha + ab));
    const float2 a1 = __ldg((const float2*)(alpha + ab + OUT_F));
    const float2 a2 = __ldg((const float2*)(alpha + ab + 2 * OUT_F));
    const float2 a3 = __ldg((const float2*)(alpha + ab + 3 * OUT_F));
    const float2 qb = __ldg((const float2*)(qbias + (long)chunk * OUT_F + o0));

    float yx = p0.x * a0.x + p1.x * a1.x + p2.x * a2.x + p3.x * a3.x + Sc * qb.x;
    float yy = p0.y * a0.y + p1.y * a1.y + p2.y * a2.y + p3.y * a3.y + Sc * qb.y;

    atomicAdd(out + o0,     yx);
    atomicAdd(out + o0 + 1, yy);
}

extern "C" void kernel_launch(void* const* d_in, const int* in_sizes, int n_in,
                              void* d_out, int out_size)
{
    const float*    x     = (const float*)d_in[0];
    const uint32_t* qw    = (const uint32_t*)d_in[1];
    const float*    alpha = (const float*)d_in[2];
    const float*    qbias = (const float*)d_in[3];
    float*          out   = (float*)d_out;

    cudaMemsetAsync(out, 0, OUT_F * sizeof(float));

    dim3 grid(NTILE, NCHUNK);
    lutgemm_kernel<<<grid, THREADS>>>(x, qw, alpha, qbias, out);
}

// round 9
// speedup vs baseline: 1.0209x; 1.0209x over previous
#include <cuda_runtime.h>
#include <stdint.h>

#define IN_F   4096
#define OUT_F  11008
#define BITS   4
#define GROUP  128

#define CHUNK    128                 // inputs per block = one dequant group
#define NCHUNK   (IN_F / CHUNK)      // 32
#define OPT      2                   // outputs per thread
#define THREADS  256
#define TILE_O   (THREADS * OPT)     // 512
#define NTILE    ((OUT_F + TILE_O - 1) / TILE_O)   // 22 (last block partial)
#define NTAB     (CHUNK / 8)         // 16 tables of 256 entries
#define NWORDS   (CHUNK / 32)        // 4 packed words per block

__global__ void __launch_bounds__(THREADS, 8) lutgemm_kernel(
    const float*    __restrict__ x,
    const uint32_t* __restrict__ qweight,
    const float*    __restrict__ alpha,
    const float*    __restrict__ qbias,
    float*          __restrict__ out)
{
    __shared__ float lut[NTAB * 256];      // 16 KB of sign-sum tables
    __shared__ float xs[CHUNK];
    __shared__ float ws[CHUNK / 32];

    const int t     = threadIdx.x;
    const int chunk = blockIdx.y;                    // 128-input group index
    const int o0    = blockIdx.x * TILE_O + 2 * t;   // this thread's 2 outputs

    // ---- stage x chunk + group sum (for the q_bias term) ----
    if (t < CHUNK) {
        float v = x[chunk * CHUNK + t];
        xs[t] = v;
        #pragma unroll
        for (int s = 16; s; s >>= 1) v += __shfl_down_sync(0xffffffffu, v, s);
        if ((t & 31) == 0) ws[t >> 5] = v;
    }
    __syncthreads();
    const float Sc = ws[0] + ws[1] + ws[2] + ws[3];   // group sum of x

    // ---- build LUTs: 256 threads x 16 gray-code-consecutive entries ----
    // Table tb covers inputs [chunk*128 + tb*8, +8); T[v] = sum_j (2*bit_j(v)-1)*x_j
    {
        const int tb = t >> 4;                 // 0..15
        const int s0 = (t & 15) * 16;          // run start (multiple of 16)
        const uint32_t g0 = (uint32_t)s0 ^ ((uint32_t)s0 >> 1);

        float x2[8];
        #pragma unroll
        for (int j = 0; j < 8; ++j) x2[j] = 2.0f * xs[tb * 8 + j];

        float acc = 0.0f;
        #pragma unroll
        for (int j = 0; j < 8; ++j)
            acc += ((g0 >> j) & 1u) ? 0.5f * x2[j] : -0.5f * x2[j];

        float* T = lut + tb * 256;
        T[g0] = acc;

        #pragma unroll
        for (int j = 1; j < 16; ++j) {
            const int k = (j & 1) ? 0 : (j & 2) ? 1 : (j & 4) ? 2 : 3;  // ctz(j)
            const uint32_t g = g0 ^ (uint32_t)(j ^ (j >> 1));           // gray(s0+j)
            acc += ((g >> k) & 1u) ? x2[k] : -x2[k];
            T[g] = acc;
        }
    }
    __syncthreads();

    if (o0 >= OUT_F) return;   // only last o-tile has idle threads

    // ---- main lookup loop: 4 words x 4 bitplanes x 2 outputs x 4 bytes ----
    float2 p0 = {0.f, 0.f}, p1 = {0.f, 0.f}, p2 = {0.f, 0.f}, p3 = {0.f, 0.f};

    #pragma unroll
    for (int wl = 0; wl < NWORDS; ++wl) {
        const int w = chunk * NWORDS + wl;
        const char* Tb = (const char*)(lut + wl * (4 * 256));
        const long base = (long)(w * BITS) * OUT_F + o0;

        const uint2 q0 = __ldg((const uint2*)(qweight + base));
        const uint2 q1 = __ldg((const uint2*)(qweight + base + OUT_F));
        const uint2 q2 = __ldg((const uint2*)(qweight + base + 2 * OUT_F));
        const uint2 q3 = __ldg((const uint2*)(qweight + base + 3 * OUT_F));

        #define LKP(dst, v)                                                     \
            dst += *(const float*)(Tb        + (((v) <<  2) & 0x3FCu))          \
                 + *(const float*)(Tb + 1024 + (((v) >>  6) & 0x3FCu))          \
                 + *(const float*)(Tb + 2048 + (((v) >> 14) & 0x3FCu))          \
                 + *(const float*)(Tb + 3072 + (((v) >> 22) & 0x3FCu))

        LKP(p0.x, q0.x); LKP(p0.y, q0.y);
        LKP(p1.x, q1.x); LKP(p1.y, q1.y);
        LKP(p2.x, q2.x); LKP(p2.y, q2.y);
        LKP(p3.x, q3.x); LKP(p3.y, q3.y);
        #undef LKP
    }

    // ---- epilogue: alpha, q_bias (one group per block), atomic accumulate ----
    const long ab = (long)(chunk * BITS) * OUT_F + o0;
    const float2 a0 = __ldg((const float2*)(alpha + ab));
    const float2 a1 = __ldg((const float2*)(alpha + ab + OUT_F));
    const float2 a2 = __ldg((const float2*)(alpha + ab + 2 * OUT_F));
    const float2 a3 = __ldg((const float2*)(alpha + ab + 3 * OUT_F));
    const float2 qb = __ldg((const float2*)(qbias + (long)chunk * OUT_F + o0));

    float yx = p0.x * a0.x + p1.x * a1.x + p2.x * a2.x + p3.x * a3.x + Sc * qb.x;
    float yy = p0.y * a0.y + p1.y * a1.y + p2.y * a2.y + p3.y * a3.y + Sc * qb.y;

    atomicAdd(out + o0,     yx);
    atomicAdd(out + o0 + 1, yy);
}

extern "C" void kernel_launch(void* const* d_in, const int* in_sizes, int n_in,
                              void* d_out, int out_size)
{
    const float*    x     = (const float*)d_in[0];
    const uint32_t* qw    = (const uint32_t*)d_in[1];
    const float*    alpha = (const float*)d_in[2];
    const float*    qbias = (const float*)d_in[3];
    float*          out   = (float*)d_out;

    cudaMemsetAsync(out, 0, OUT_F * sizeof(float));

    dim3 grid(NTILE, NCHUNK);
    lutgemm_kernel<<<grid, THREADS>>>(x, qw, alpha, qbias, out);
}